// round 16
// baseline (speedup 1.0000x reference)
#include <cuda_runtime.h>
#include <cuda_fp16.h>
#include <cstdint>

// Problem constants
#define Bv   2
#define Sv   2048
#define Hv   16
#define Dv   64
#define Ev   1024
#define MTOK (Bv * Sv)   // 4096 tokens
#define EE   (Ev * Ev)

// ---------------------------------------------------------------------------
// Scratch (device globals — no allocation allowed). Everything fp16 single.
// ---------------------------------------------------------------------------
__device__ __half g_qh [MTOK * Ev];
__device__ __half g_kh [MTOK * Ev];
__device__ __half g_vh [MTOK * Ev];
__device__ __half g_aoh[MTOK * Ev];
__device__ __half g_xh [MTOK * Ev];
__device__ __half g_wth[4][EE];   // W^T fp16  [N,K]

// ---------------------------------------------------------------------------
// PTX helpers
// ---------------------------------------------------------------------------
__device__ __forceinline__ uint32_t smem_to_u32(const void* p) {
    uint32_t a;
    asm("{ .reg .u64 t; cvta.to.shared.u64 t, %1; cvt.u32.u64 %0, t; }"
        : "=r"(a) : "l"(p));
    return a;
}
__device__ __forceinline__ void cp_async16(uint32_t smem, const void* gmem) {
    asm volatile("cp.async.cg.shared.global [%0], [%1], 16;"
                 :: "r"(smem), "l"(gmem));
}
#define CP_COMMIT() asm volatile("cp.async.commit_group;" ::: "memory")
#define CP_WAIT1()  asm volatile("cp.async.wait_group 1;"  ::: "memory")

__device__ __forceinline__ void ldsm_x4(uint32_t* r, uint32_t addr) {
    asm volatile("ldmatrix.sync.aligned.m8n8.x4.shared.b16 {%0,%1,%2,%3}, [%4];"
                 : "=r"(r[0]), "=r"(r[1]), "=r"(r[2]), "=r"(r[3]) : "r"(addr));
}
__device__ __forceinline__ void ldsm_x4_t(uint32_t* r, uint32_t addr) {
    asm volatile("ldmatrix.sync.aligned.m8n8.x4.trans.shared.b16 {%0,%1,%2,%3}, [%4];"
                 : "=r"(r[0]), "=r"(r[1]), "=r"(r[2]), "=r"(r[3]) : "r"(addr));
}
__device__ __forceinline__ void mma16816(float* d, const uint32_t* a,
                                         uint32_t b0, uint32_t b1) {
    asm volatile(
        "mma.sync.aligned.m16n8k16.row.col.f32.f16.f16.f32 "
        "{%0,%1,%2,%3}, {%4,%5,%6,%7}, {%8,%9}, {%0,%1,%2,%3};"
        : "+f"(d[0]), "+f"(d[1]), "+f"(d[2]), "+f"(d[3])
        : "r"(a[0]), "r"(a[1]), "r"(a[2]), "r"(a[3]), "r"(b0), "r"(b1));
}
// {lo: rn(a), hi: rn(b)} fp16x2 pack
__device__ __forceinline__ uint32_t pack_f16(float a, float b) {
    uint32_t r;
    asm("cvt.rn.f16x2.f32 %0, %1, %2;" : "=r"(r) : "f"(b), "f"(a));
    return r;
}
__device__ __forceinline__ float ex2(float x) {
    float r; asm("ex2.approx.f32 %0, %1;" : "=f"(r) : "f"(x)); return r;
}
// two fp16 2^x in one MUFU op
__device__ __forceinline__ uint32_t ex2h2(uint32_t a) {
    uint32_t r; asm("ex2.approx.f16x2 %0, %1;" : "=r"(r) : "r"(a)); return r;
}

// ---------------------------------------------------------------------------
// fp32 -> fp16, vectorized
// ---------------------------------------------------------------------------
__global__ __launch_bounds__(256) void split_hi4(const float* __restrict__ in,
                                                 __half* __restrict__ hi, int n) {
    int i = (blockIdx.x * 256 + threadIdx.x) * 4;
    if (i < n) {
        float4 v = *(const float4*)(in + i);
        *(uint2*)(hi + i) = make_uint2(pack_f16(v.x, v.y), pack_f16(v.z, v.w));
    }
}

// ---------------------------------------------------------------------------
// Transpose to fp16, all 4 weights in one launch
// ---------------------------------------------------------------------------
__global__ __launch_bounds__(256) void transpose4(
    const float* __restrict__ W0, const float* __restrict__ W1,
    const float* __restrict__ W2, const float* __restrict__ W3,
    __half* __restrict__ ThB) {
    __shared__ float t[32][33];
    const float* W = (blockIdx.z == 0) ? W0 : (blockIdx.z == 1) ? W1
                    : (blockIdx.z == 2) ? W2 : W3;
    __half* Th = ThB + (size_t)blockIdx.z * EE;
    int n0 = blockIdx.x * 32, k0 = blockIdx.y * 32;
    int tx = threadIdx.x, ty = threadIdx.y;
    for (int i = ty; i < 32; i += 8)
        t[i][tx] = W[(size_t)(k0 + i) * Ev + n0 + tx];
    __syncthreads();
    for (int i = ty; i < 32; i += 8)
        Th[(size_t)(n0 + i) * Ev + k0 + tx] = __float2half_rn(t[tx][i]);
}

// ---------------------------------------------------------------------------
// HMMA GEMM fp16 (single-term): C = A @ B^T.
// 128x128x32 tile, 3-stage cp.async, 8 warps, 2 CTAs/SM.
// MODE 0: out-projection (W index 3), fp32 C out.
// MODE 1: fused QKV (w = bx>>3), fp16 out (Q/K/V).
// ---------------------------------------------------------------------------
#define BM 128
#define BN 128
#define BK 32
#define STAGES 3
#define TILE_B  8192u                 // 128*32*2B
#define STAGE_B (2u * TILE_B)         // Ah, Bh
#define GEMM_SMEM (STAGES * STAGE_B)  // 48 KB
#define NCHUNK (Ev / BK)              // 32

template <int MODE>
__global__ __launch_bounds__(256, 2) void gemm_hmma_f16(
    const __half* __restrict__ Ah,
    const __half* __restrict__ WTh,
    float* __restrict__ C,
    __half* __restrict__ O0h, __half* __restrict__ O1h, __half* __restrict__ O2h) {
    extern __shared__ char smc[];
    const uint32_t sbase = smem_to_u32(smc);
    const int tid  = threadIdx.x;
    const int lane = tid & 31;
    const int wid  = tid >> 5;
    const int warp_m = wid & 1;
    const int warp_n = wid >> 1;
    const int m0 = blockIdx.y * BM;
    const int K = Ev, N = Ev;

    const __half* Bh;
    int n0, w = 0;
    if (MODE == 0) {
        Bh = WTh + (size_t)3 * EE;
        n0 = blockIdx.x * BN;
    } else {
        w = blockIdx.x >> 3;
        n0 = (blockIdx.x & 7) * BN;
        Bh = WTh + (size_t)w * EE;
    }

    auto load_stage = [&](int kc, int s) {
        uint32_t st = sbase + (uint32_t)s * STAGE_B;
#pragma unroll
        for (int half = 0; half < 2; half++) {
            int q   = tid + half * 256;
            int row = q >> 2;
            int ch  = q & 3;
            uint32_t sw = (uint32_t)(row * 64 + ((ch ^ ((row >> 1) & 3)) * 16));
            size_t ga = (size_t)(m0 + row) * K + kc * BK + ch * 8;
            size_t gb = (size_t)(n0 + row) * K + kc * BK + ch * 8;
            cp_async16(st + sw,        Ah + ga);
            cp_async16(st + 8192 + sw, Bh + gb);
        }
    };

    float acc[4][4][4];
#pragma unroll
    for (int mt = 0; mt < 4; mt++)
#pragma unroll
        for (int nt = 0; nt < 4; nt++)
#pragma unroll
            for (int e = 0; e < 4; e++) acc[mt][nt][e] = 0.0f;

    load_stage(0, 0); CP_COMMIT();
    load_stage(1, 1); CP_COMMIT();

    const int sub = lane >> 3;
    const int r8  = lane & 7;

    for (int c = 0; c < NCHUNK; c++) {
        CP_WAIT1();
        __syncthreads();
        uint32_t st = sbase + (uint32_t)(c % STAGES) * STAGE_B;

#pragma unroll
        for (int ks = 0; ks < 2; ks++) {
            const int ch = ks * 2 + (sub >> 1);
            uint32_t ah[4][4];
#pragma unroll
            for (int mt = 0; mt < 4; mt++) {
                int row = warp_m * 64 + mt * 16 + (sub & 1) * 8 + r8;
                ldsm_x4(ah[mt], st + (uint32_t)(row * 64 + ((ch ^ ((row >> 1) & 3)) * 16)));
            }
            uint32_t bh[2][4];
#pragma unroll
            for (int np = 0; np < 2; np++) {
                int row = warp_n * 32 + np * 16 + (sub & 1) * 8 + r8;
                ldsm_x4(bh[np], st + 8192 +
                        (uint32_t)(row * 64 + ((ch ^ ((row >> 1) & 3)) * 16)));
            }
#pragma unroll
            for (int mt = 0; mt < 4; mt++)
#pragma unroll
                for (int nt = 0; nt < 4; nt++)
                    mma16816(acc[mt][nt], ah[mt],
                             bh[nt >> 1][nt & 1], bh[nt >> 1][2 + (nt & 1)]);
        }
        __syncthreads();
        if (c + STAGES - 1 < NCHUNK) load_stage(c + STAGES - 1, (c + STAGES - 1) % STAGES);
        CP_COMMIT();
    }

    const int g   = lane >> 2;
    const int tig = lane & 3;
    __half* Ch = nullptr;
    if (MODE == 1) Ch = (w == 0) ? O0h : (w == 1) ? O1h : O2h;
#pragma unroll
    for (int mt = 0; mt < 4; mt++) {
        int r0 = m0 + warp_m * 64 + mt * 16 + g;
#pragma unroll
        for (int nt = 0; nt < 4; nt++) {
            int col = n0 + warp_n * 32 + nt * 8 + tig * 2;
            float* a = acc[mt][nt];
            if (MODE == 1) {
                *(uint32_t*)&Ch[(size_t)r0 * N + col]       = pack_f16(a[0], a[1]);
                *(uint32_t*)&Ch[(size_t)(r0 + 8) * N + col] = pack_f16(a[2], a[3]);
            } else {
                *(float2*)&C[(size_t)r0 * N + col]       = make_float2(a[0], a[1]);
                *(float2*)&C[(size_t)(r0 + 8) * N + col] = make_float2(a[2], a[3]);
            }
        }
    }
}

// ---------------------------------------------------------------------------
// HMMA flash attention (causal), all-fp16, SOFTWARE-PIPELINED across KV tiles:
// S_{j+1} MMAs are issued BEFORE softmax_j so the tensor pipe stays busy while
// the FMA/MUFU softmax chain of tile j executes (warps issue in order).
// 128 threads (4 warps x 16 q-rows = 64 q-rows), KV tile 64, 3-stage KV ring.
// Smem: Q 8K | 3 x (Kh Vh @8K) = 56 KB. launch_bounds(128,2) — a FLOOR, no
// forced reg squeeze (R12: forced caps spill the MMA mainloop).
// Per-tile math identical to R15 (same order) -> rel_err unchanged.
// ---------------------------------------------------------------------------
#define ATT_STAGE 16384
#define ATT_NSTG  3
#define ATT_SMEM  (8192 + ATT_NSTG * ATT_STAGE)   // 56 KB
#define ONES_H2 0x3C003C00u               // {1.0h, 1.0h}

__global__ __launch_bounds__(128, 2) void attn_hmma(
    const __half* __restrict__ Qh,
    const __half* __restrict__ Kh,
    const __half* __restrict__ Vh,
    __half* __restrict__ AOh) {
    extern __shared__ char smc[];
    const uint32_t sb = smem_to_u32(smc);
    const int tid = threadIdx.x, lane = tid & 31, wid = tid >> 5;
    const int qt = (int)gridDim.x - 1 - (int)blockIdx.x;  // heavy tiles first
    const int bh = blockIdx.y;
    const int b  = bh >> 4, h = bh & 15;
    const size_t base = (size_t)(b * Sv) * Ev + h * Dv;

    const int sub = lane >> 3, r8 = lane & 7, g = lane >> 2, tig = lane & 3;

    const uint32_t sQ = sb;
    auto stage = [&](int s) { return sb + 8192 + (uint32_t)s * ATT_STAGE; };
    auto sw = [](int row, int ch) {
        return (uint32_t)(row * 128 + ((ch ^ (row & 7)) * 16));
    };

    const int ntiles = qt + 1;
    const int wr0 = qt * 64 + wid * 16;
    const float Cc = 0.125f * 1.44269504f;     // scale * log2(e)

    // Q tile (64 rows) + KV tile 0 -> cp.async group 0; KV tile 1 -> group 1
    {
        const __half* q0 = Qh + base + (size_t)(qt * 64) * Ev;
        for (int i = tid; i < 512; i += 128) {
            int row = i >> 3, ch = i & 7;
            cp_async16(sQ + sw(row, ch), q0 + (size_t)row * Ev + ch * 8);
        }
    }
    auto loadKV = [&](int j, int s) {
        uint32_t st = stage(s);
        const __half* kh = Kh + base + (size_t)(j * 64) * Ev;
        const __half* vh = Vh + base + (size_t)(j * 64) * Ev;
#pragma unroll
        for (int rep = 0; rep < 4; rep++) {
            int i = tid + rep * 128;           // 0..511
            int row = i >> 3, ch = i & 7;
            size_t off = (size_t)row * Ev + ch * 8;
            uint32_t d = sw(row, ch);
            cp_async16(st + d,        kh + off);
            cp_async16(st + 8192 + d, vh + off);
        }
    };
    loadKV(0, 0); CP_COMMIT();
    if (ntiles > 1) loadKV(1, 1);
    CP_COMMIT();
    CP_WAIT1();            // group 0 (Q + KV0) complete; group 1 may be in flight
    __syncthreads();       // visible to all warps

    // Q fragments (registers, reused for all tiles)
    uint32_t qh[4][4];
#pragma unroll
    for (int ks = 0; ks < 4; ks++) {
        int row = wid * 16 + (sub & 1) * 8 + r8;
        int ch  = ks * 2 + (sub >> 1);
        ldsm_x4(qh[ks], sQ + sw(row, ch));
    }

    // S = Q K^T for one tile, from K at smem stage 'st', into dst
    auto compute_S = [&](float (&dst)[8][4], uint32_t st) {
#pragma unroll
        for (int nt = 0; nt < 8; nt++)
#pragma unroll
            for (int e = 0; e < 4; e++) dst[nt][e] = 0.f;
#pragma unroll
        for (int ks = 0; ks < 4; ks++) {
            uint32_t kh4[4][4];
#pragma unroll
            for (int np = 0; np < 4; np++) {
                int row = np * 16 + (sub & 1) * 8 + r8;
                int ch  = ks * 2 + (sub >> 1);
                ldsm_x4(kh4[np], st + sw(row, ch));
            }
#pragma unroll
            for (int nt = 0; nt < 8; nt++)
                mma16816(dst[nt], qh[ks],
                         kh4[nt >> 1][nt & 1], kh4[nt >> 1][2 + (nt & 1)]);
        }
    };

    float m0 = -1e30f, m1 = -1e30f, l0 = 0.f, l1 = 0.f;
    float o[8][4];
#pragma unroll
    for (int nt = 0; nt < 8; nt++)
#pragma unroll
        for (int e = 0; e < 4; e++) o[nt][e] = 0.f;

    float sA[8][4], sB[8][4];
    compute_S(sA, stage(0));   // prologue: S_0

    // One pipelined step: consumes S_j in 'cur', produces S_{j+1} in 'nxt'.
    auto step = [&](int j, float (&cur)[8][4], float (&nxt)[8][4]) {
        __syncthreads();                      // all warps done with stage (j-1)%3
        if (j + 2 < ntiles) loadKV(j + 2, (j + 2) % ATT_NSTG);
        CP_COMMIT();                          // uniform group accounting
        if (j + 1 < ntiles) {
            CP_WAIT1();                       // KV_{j+1} landed (only KV_{j+2} pending)
            __syncthreads();                  // visible to all warps
            compute_S(nxt, stage((j + 1) % ATT_NSTG));   // fills tensor pipe
        }

        // ---- causal mask (diagonal = last tile) ----
        if (j == ntiles - 1) {
            int colb = j * 64;
            int row0 = wr0 + g, row1 = row0 + 8;
#pragma unroll
            for (int nt = 0; nt < 8; nt++) {
                int c0 = colb + nt * 8 + tig * 2;
                if (c0     > row0) cur[nt][0] = -1e30f;
                if (c0 + 1 > row0) cur[nt][1] = -1e30f;
                if (c0     > row1) cur[nt][2] = -1e30f;
                if (c0 + 1 > row1) cur[nt][3] = -1e30f;
            }
        }

        // ---- online softmax (overlaps tensor drain of S_{j+1}) ----
        float mx0 = -1e30f, mx1 = -1e30f;
#pragma unroll
        for (int nt = 0; nt < 8; nt++) {
            mx0 = fmaxf(mx0, fmaxf(cur[nt][0], cur[nt][1]));
            mx1 = fmaxf(mx1, fmaxf(cur[nt][2], cur[nt][3]));
        }
        mx0 = fmaxf(mx0, __shfl_xor_sync(0xffffffffu, mx0, 1));
        mx0 = fmaxf(mx0, __shfl_xor_sync(0xffffffffu, mx0, 2));
        mx1 = fmaxf(mx1, __shfl_xor_sync(0xffffffffu, mx1, 1));
        mx1 = fmaxf(mx1, __shfl_xor_sync(0xffffffffu, mx1, 2));
        float nm0 = fmaxf(m0, mx0), nm1 = fmaxf(m1, mx1);
        float cr0 = ex2((m0 - nm0) * Cc), cr1 = ex2((m1 - nm1) * Cc);
        m0 = nm0; m1 = nm1;
        const float mm0 = m0 * Cc, mm1 = m1 * Cc;

        uint32_t ph[4][4];
#pragma unroll
        for (int j2 = 0; j2 < 4; j2++) {
            float* e0 = cur[2 * j2];
            float* e1 = cur[2 * j2 + 1];
            ph[j2][0] = ex2h2(pack_f16(fmaf(e0[0], Cc, -mm0), fmaf(e0[1], Cc, -mm0)));
            ph[j2][1] = ex2h2(pack_f16(fmaf(e0[2], Cc, -mm1), fmaf(e0[3], Cc, -mm1)));
            ph[j2][2] = ex2h2(pack_f16(fmaf(e1[0], Cc, -mm0), fmaf(e1[1], Cc, -mm0)));
            ph[j2][3] = ex2h2(pack_f16(fmaf(e1[2], Cc, -mm1), fmaf(e1[3], Cc, -mm1)));
        }

#pragma unroll
        for (int nt = 0; nt < 8; nt++) {
            o[nt][0] *= cr0; o[nt][1] *= cr0;
            o[nt][2] *= cr1; o[nt][3] *= cr1;
        }

        // row sums via MMA with B = ones (off the critical path)
        float ls[4] = {0.f, 0.f, 0.f, 0.f};
#pragma unroll
        for (int ks = 0; ks < 4; ks++)
            mma16816(ls, ph[ks], ONES_H2, ONES_H2);
        l0 = l0 * cr0 + ls[0];
        l1 = l1 * cr1 + ls[2];

        // ---- O += P Vh (V from stage j%3; ldmatrix.trans) ----
        uint32_t stv = stage(j % ATT_NSTG) + 8192;
#pragma unroll
        for (int ks = 0; ks < 4; ks++) {
#pragma unroll
            for (int dv = 0; dv < 4; dv++) {
                int row = ks * 16 + (sub & 1) * 8 + r8;
                int ch  = dv * 2 + (sub >> 1);
                uint32_t vh4[4];
                ldsm_x4_t(vh4, stv + sw(row, ch));
                mma16816(o[2 * dv],     ph[ks], vh4[0], vh4[1]);
                mma16816(o[2 * dv + 1], ph[ks], vh4[2], vh4[3]);
            }
        }
    };

    int j = 0;
    for (; j + 1 < ntiles; j += 2) {
        step(j,     sA, sB);
        step(j + 1, sB, sA);
    }
    if (j < ntiles) step(j, sA, sB);

    // ---- normalize + write AO fp16 ----
    float i0 = 1.0f / l0, i1 = 1.0f / l1;
    int t0 = qt * 64 + wid * 16 + g, t1 = t0 + 8;
#pragma unroll
    for (int nt = 0; nt < 8; nt++) {
        int col = nt * 8 + tig * 2;
        *(uint32_t*)&AOh[base + (size_t)t0 * Ev + col] =
            pack_f16(o[nt][0] * i0, o[nt][1] * i0);
        *(uint32_t*)&AOh[base + (size_t)t1 * Ev + col] =
            pack_f16(o[nt][2] * i1, o[nt][3] * i1);
    }
}

// ---------------------------------------------------------------------------
// Launch
// ---------------------------------------------------------------------------
extern "C" void kernel_launch(void* const* d_in, const int* in_sizes, int n_in,
                              void* d_out, int out_size) {
    const float* x  = (const float*)d_in[0];
    const float* Wq = (const float*)d_in[1];
    const float* Wk = (const float*)d_in[2];
    const float* Wv = (const float*)d_in[3];
    const float* Wo = (const float*)d_in[4];
    float* out = (float*)d_out;

    __half *qh, *kh, *vh, *aoh, *xh, *wth;
    cudaGetSymbolAddress((void**)&qh,  g_qh);
    cudaGetSymbolAddress((void**)&kh,  g_kh);
    cudaGetSymbolAddress((void**)&vh,  g_vh);
    cudaGetSymbolAddress((void**)&aoh, g_aoh);
    cudaGetSymbolAddress((void**)&xh,  g_xh);
    cudaGetSymbolAddress((void**)&wth, g_wth);

    static bool attr_set = false;
    if (!attr_set) {
        cudaFuncSetAttribute(gemm_hmma_f16<0>,
                             cudaFuncAttributeMaxDynamicSharedMemorySize, GEMM_SMEM);
        cudaFuncSetAttribute(gemm_hmma_f16<1>,
                             cudaFuncAttributeMaxDynamicSharedMemorySize, GEMM_SMEM);
        cudaFuncSetAttribute(attn_hmma,
                             cudaFuncAttributeMaxDynamicSharedMemorySize, ATT_SMEM);
        attr_set = true;
    }

    const int nElem = MTOK * Ev;

    // 1. x -> fp16
    split_hi4<<<nElem / 1024, 256>>>(x, xh, nElem);

    // 2. transpose all 4 weights to fp16 [N,K]
    dim3 tGrid(Ev / 32, Ev / 32, 4), tBlk(32, 8);
    transpose4<<<tGrid, tBlk>>>(Wq, Wk, Wv, Wo, wth);

    // 3. fused QKV projection (N = 3072, single-term fp16)
    dim3 qkvGrid(24, MTOK / BM);
    gemm_hmma_f16<1><<<qkvGrid, 256, GEMM_SMEM>>>(
        xh, wth, nullptr, qh, kh, vh);

    // 4. flash attention (software-pipelined S)
    dim3 attnGrid(Sv / 64, Bv * Hv);   // (32, 32)
    attn_hmma<<<attnGrid, 128, ATT_SMEM>>>(qh, kh, vh, aoh);

    // 5. output projection -> fp32 out
    dim3 oGrid(Ev / BN, MTOK / BM);
    gemm_hmma_f16<0><<<oGrid, 256, GEMM_SMEM>>>(
        aoh, wth, out, nullptr, nullptr, nullptr);
}

// round 17
// speedup vs baseline: 1.1028x; 1.1028x over previous
#include <cuda_runtime.h>
#include <cuda_fp16.h>
#include <cstdint>

// Problem constants
#define Bv   2
#define Sv   2048
#define Hv   16
#define Dv   64
#define Ev   1024
#define MTOK (Bv * Sv)   // 4096 tokens
#define EE   (Ev * Ev)

// ---------------------------------------------------------------------------
// Scratch (device globals — no allocation allowed). Everything fp16 single.
// ---------------------------------------------------------------------------
__device__ __half g_qh [MTOK * Ev];
__device__ __half g_kh [MTOK * Ev];
__device__ __half g_vh [MTOK * Ev];
__device__ __half g_aoh[MTOK * Ev];
__device__ __half g_xh [MTOK * Ev];
__device__ __half g_wth[4][EE];   // W^T fp16  [N,K]

// ---------------------------------------------------------------------------
// PTX helpers
// ---------------------------------------------------------------------------
__device__ __forceinline__ uint32_t smem_to_u32(const void* p) {
    uint32_t a;
    asm("{ .reg .u64 t; cvta.to.shared.u64 t, %1; cvt.u32.u64 %0, t; }"
        : "=r"(a) : "l"(p));
    return a;
}
__device__ __forceinline__ void cp_async16(uint32_t smem, const void* gmem) {
    asm volatile("cp.async.cg.shared.global [%0], [%1], 16;"
                 :: "r"(smem), "l"(gmem));
}
#define CP_COMMIT() asm volatile("cp.async.commit_group;" ::: "memory")
#define CP_WAIT1()  asm volatile("cp.async.wait_group 1;"  ::: "memory")

__device__ __forceinline__ void ldsm_x4(uint32_t* r, uint32_t addr) {
    asm volatile("ldmatrix.sync.aligned.m8n8.x4.shared.b16 {%0,%1,%2,%3}, [%4];"
                 : "=r"(r[0]), "=r"(r[1]), "=r"(r[2]), "=r"(r[3]) : "r"(addr));
}
__device__ __forceinline__ void ldsm_x4_t(uint32_t* r, uint32_t addr) {
    asm volatile("ldmatrix.sync.aligned.m8n8.x4.trans.shared.b16 {%0,%1,%2,%3}, [%4];"
                 : "=r"(r[0]), "=r"(r[1]), "=r"(r[2]), "=r"(r[3]) : "r"(addr));
}
__device__ __forceinline__ void mma16816(float* d, const uint32_t* a,
                                         uint32_t b0, uint32_t b1) {
    asm volatile(
        "mma.sync.aligned.m16n8k16.row.col.f32.f16.f16.f32 "
        "{%0,%1,%2,%3}, {%4,%5,%6,%7}, {%8,%9}, {%0,%1,%2,%3};"
        : "+f"(d[0]), "+f"(d[1]), "+f"(d[2]), "+f"(d[3])
        : "r"(a[0]), "r"(a[1]), "r"(a[2]), "r"(a[3]), "r"(b0), "r"(b1));
}
// {lo: rn(a), hi: rn(b)} fp16x2 pack
__device__ __forceinline__ uint32_t pack_f16(float a, float b) {
    uint32_t r;
    asm("cvt.rn.f16x2.f32 %0, %1, %2;" : "=r"(r) : "f"(b), "f"(a));
    return r;
}
__device__ __forceinline__ float ex2(float x) {
    float r; asm("ex2.approx.f32 %0, %1;" : "=f"(r) : "f"(x)); return r;
}
// two fp16 2^x in one MUFU op
__device__ __forceinline__ uint32_t ex2h2(uint32_t a) {
    uint32_t r; asm("ex2.approx.f16x2 %0, %1;" : "=r"(r) : "r"(a)); return r;
}

// shared 128B-row swizzle: rows of 128 bytes, 8 chunks of 16B, ch ^= row&7
__device__ __forceinline__ uint32_t sw128(int row, int ch) {
    return (uint32_t)(row * 128 + ((ch ^ (row & 7)) * 16));
}

// ---------------------------------------------------------------------------
// fp32 -> fp16, vectorized
// ---------------------------------------------------------------------------
__global__ __launch_bounds__(256) void split_hi4(const float* __restrict__ in,
                                                 __half* __restrict__ hi, int n) {
    int i = (blockIdx.x * 256 + threadIdx.x) * 4;
    if (i < n) {
        float4 v = *(const float4*)(in + i);
        *(uint2*)(hi + i) = make_uint2(pack_f16(v.x, v.y), pack_f16(v.z, v.w));
    }
}

// ---------------------------------------------------------------------------
// Transpose to fp16, all 4 weights in one launch
// ---------------------------------------------------------------------------
__global__ __launch_bounds__(256) void transpose4(
    const float* __restrict__ W0, const float* __restrict__ W1,
    const float* __restrict__ W2, const float* __restrict__ W3,
    __half* __restrict__ ThB) {
    __shared__ float t[32][33];
    const float* W = (blockIdx.z == 0) ? W0 : (blockIdx.z == 1) ? W1
                    : (blockIdx.z == 2) ? W2 : W3;
    __half* Th = ThB + (size_t)blockIdx.z * EE;
    int n0 = blockIdx.x * 32, k0 = blockIdx.y * 32;
    int tx = threadIdx.x, ty = threadIdx.y;
    for (int i = ty; i < 32; i += 8)
        t[i][tx] = W[(size_t)(k0 + i) * Ev + n0 + tx];
    __syncthreads();
    for (int i = ty; i < 32; i += 8)
        Th[(size_t)(n0 + i) * Ev + k0 + tx] = __float2half_rn(t[tx][i]);
}

// ---------------------------------------------------------------------------
// HMMA GEMM fp16 (single-term): C = A @ B^T.
// 128x128 CTA tile, BK=64 (32 barriers/CTA instead of 64 — longer MMA runs
// between syncs), 3-stage cp.async ring (96 KB), 8 warps, 2 CTAs/SM.
// Accumulation order identical to BK=32 version (same 64 k16 steps).
// MODE 0: out-projection (W index 3), fp32 C out.
// MODE 1: fused QKV (w = bx>>3), fp16 out (Q/K/V).
// ---------------------------------------------------------------------------
#define BM 128
#define BN 128
#define BK 64
#define STAGES 3
#define TILE_B  16384u                // 128 rows * 128B
#define STAGE_B (2u * TILE_B)         // Ah, Bh = 32 KB
#define GEMM_SMEM (STAGES * STAGE_B)  // 96 KB
#define NCHUNK (Ev / BK)              // 16

template <int MODE>
__global__ __launch_bounds__(256, 2) void gemm_hmma_f16(
    const __half* __restrict__ Ah,
    const __half* __restrict__ WTh,
    float* __restrict__ C,
    __half* __restrict__ O0h, __half* __restrict__ O1h, __half* __restrict__ O2h) {
    extern __shared__ char smc[];
    const uint32_t sbase = smem_to_u32(smc);
    const int tid  = threadIdx.x;
    const int lane = tid & 31;
    const int wid  = tid >> 5;
    const int warp_m = wid & 1;
    const int warp_n = wid >> 1;
    const int m0 = blockIdx.y * BM;
    const int K = Ev, N = Ev;

    const __half* Bh;
    int n0, w = 0;
    if (MODE == 0) {
        Bh = WTh + (size_t)3 * EE;
        n0 = blockIdx.x * BN;
    } else {
        w = blockIdx.x >> 3;
        n0 = (blockIdx.x & 7) * BN;
        Bh = WTh + (size_t)w * EE;
    }

    auto load_stage = [&](int kc, int s) {
        uint32_t st = sbase + (uint32_t)s * STAGE_B;
#pragma unroll
        for (int rep = 0; rep < 4; rep++) {
            int i = tid + rep * 256;          // 0..1023
            int row = i >> 3;
            int ch  = i & 7;
            uint32_t d = sw128(row, ch);
            size_t ga = (size_t)(m0 + row) * K + kc * BK + ch * 8;
            size_t gb = (size_t)(n0 + row) * K + kc * BK + ch * 8;
            cp_async16(st + d,          Ah + ga);
            cp_async16(st + TILE_B + d, Bh + gb);
        }
    };

    float acc[4][4][4];
#pragma unroll
    for (int mt = 0; mt < 4; mt++)
#pragma unroll
        for (int nt = 0; nt < 4; nt++)
#pragma unroll
            for (int e = 0; e < 4; e++) acc[mt][nt][e] = 0.0f;

    load_stage(0, 0); CP_COMMIT();
    load_stage(1, 1); CP_COMMIT();

    const int sub = lane >> 3;
    const int r8  = lane & 7;

    for (int c = 0; c < NCHUNK; c++) {
        CP_WAIT1();
        __syncthreads();
        uint32_t st = sbase + (uint32_t)(c % STAGES) * STAGE_B;

#pragma unroll
        for (int ks = 0; ks < 4; ks++) {
            const int ch = ks * 2 + (sub >> 1);
            uint32_t ah[4][4];
#pragma unroll
            for (int mt = 0; mt < 4; mt++) {
                int row = warp_m * 64 + mt * 16 + (sub & 1) * 8 + r8;
                ldsm_x4(ah[mt], st + sw128(row, ch));
            }
            uint32_t bh[2][4];
#pragma unroll
            for (int np = 0; np < 2; np++) {
                int row = warp_n * 32 + np * 16 + (sub & 1) * 8 + r8;
                ldsm_x4(bh[np], st + TILE_B + sw128(row, ch));
            }
#pragma unroll
            for (int mt = 0; mt < 4; mt++)
#pragma unroll
                for (int nt = 0; nt < 4; nt++)
                    mma16816(acc[mt][nt], ah[mt],
                             bh[nt >> 1][nt & 1], bh[nt >> 1][2 + (nt & 1)]);
        }
        __syncthreads();
        if (c + STAGES - 1 < NCHUNK) load_stage(c + STAGES - 1, (c + STAGES - 1) % STAGES);
        CP_COMMIT();
    }

    const int g   = lane >> 2;
    const int tig = lane & 3;
    __half* Ch = nullptr;
    if (MODE == 1) Ch = (w == 0) ? O0h : (w == 1) ? O1h : O2h;
#pragma unroll
    for (int mt = 0; mt < 4; mt++) {
        int r0 = m0 + warp_m * 64 + mt * 16 + g;
#pragma unroll
        for (int nt = 0; nt < 4; nt++) {
            int col = n0 + warp_n * 32 + nt * 8 + tig * 2;
            float* a = acc[mt][nt];
            if (MODE == 1) {
                *(uint32_t*)&Ch[(size_t)r0 * N + col]       = pack_f16(a[0], a[1]);
                *(uint32_t*)&Ch[(size_t)(r0 + 8) * N + col] = pack_f16(a[2], a[3]);
            } else {
                *(float2*)&C[(size_t)r0 * N + col]       = make_float2(a[0], a[1]);
                *(float2*)&C[(size_t)(r0 + 8) * N + col] = make_float2(a[2], a[3]);
            }
        }
    }
}

// ---------------------------------------------------------------------------
// HMMA flash attention (causal), all-fp16 — EXACT R15 form (73.9 us, 147 regs,
// 3 CTAs/SM). R16 showed software-pipelining S costs ~80 regs and drops a CTA:
// intra-warp ILP trades 1:1 against occupancy here. Do not re-add.
// 128 threads (4 warps x 16 q-rows = 64 q-rows), KV tile 64, 2-stage.
// Smem: Q 8K | 2 x (Kh Vh @8K) = 40 KB.
// S = Qh*Kh ; P via ex2.approx.f16x2 ; O += Ph*Vh.
// Row sums via MMA with B = ones (off the critical path).
// ---------------------------------------------------------------------------
#define ATT_STAGE 16384
#define ATT_SMEM (8192 + 2 * ATT_STAGE)   // 40 KB
#define ONES_H2 0x3C003C00u               // {1.0h, 1.0h}

__global__ __launch_bounds__(128, 3) void attn_hmma(
    const __half* __restrict__ Qh,
    const __half* __restrict__ Kh,
    const __half* __restrict__ Vh,
    __half* __restrict__ AOh) {
    extern __shared__ char smc[];
    const uint32_t sb = smem_to_u32(smc);
    const int tid = threadIdx.x, lane = tid & 31, wid = tid >> 5;
    const int qt = (int)gridDim.x - 1 - (int)blockIdx.x;  // heavy tiles first
    const int bh = blockIdx.y;
    const int b  = bh >> 4, h = bh & 15;
    const size_t base = (size_t)(b * Sv) * Ev + h * Dv;

    const int sub = lane >> 3, r8 = lane & 7, g = lane >> 2, tig = lane & 3;

    const uint32_t sQ = sb;
    auto stage = [&](int s) { return sb + 8192 + (uint32_t)s * ATT_STAGE; };

    // Q tile (64 rows) — part of cp.async group 0
    {
        const __half* q0 = Qh + base + (size_t)(qt * 64) * Ev;
        for (int i = tid; i < 512; i += 128) {
            int row = i >> 3, ch = i & 7;
            cp_async16(sQ + sw128(row, ch), q0 + (size_t)row * Ev + ch * 8);
        }
    }
    auto loadKV = [&](int j, int s) {
        uint32_t st = stage(s);
        const __half* kh = Kh + base + (size_t)(j * 64) * Ev;
        const __half* vh = Vh + base + (size_t)(j * 64) * Ev;
#pragma unroll
        for (int rep = 0; rep < 4; rep++) {
            int i = tid + rep * 128;           // 0..511
            int row = i >> 3, ch = i & 7;
            size_t off = (size_t)row * Ev + ch * 8;
            uint32_t d = sw128(row, ch);
            cp_async16(st + d,        kh + off);
            cp_async16(st + 8192 + d, vh + off);
        }
    };
    loadKV(0, 0); CP_COMMIT();

    const int ntiles = qt + 1;
    const int wr0 = qt * 64 + wid * 16;
    const float Cc = 0.125f * 1.44269504f;     // scale * log2(e)

    float m0 = -1e30f, m1 = -1e30f, l0 = 0.f, l1 = 0.f;
    float o[8][4];
#pragma unroll
    for (int nt = 0; nt < 8; nt++)
#pragma unroll
        for (int e = 0; e < 4; e++) o[nt][e] = 0.f;
    uint32_t qh[4][4];

    for (int j = 0; j < ntiles; j++) {
        __syncthreads();
        if (j + 1 < ntiles) loadKV(j + 1, (j + 1) & 1);
        CP_COMMIT();
        CP_WAIT1();
        __syncthreads();
        uint32_t st = stage(j & 1);

        if (j == 0) {
#pragma unroll
            for (int ks = 0; ks < 4; ks++) {
                int row = wid * 16 + (sub & 1) * 8 + r8;
                int ch  = ks * 2 + (sub >> 1);
                ldsm_x4(qh[ks], sQ + sw128(row, ch));
            }
        }

        // ---- S = Q K^T (single-term fp16) ----
        float s[8][4];
#pragma unroll
        for (int nt = 0; nt < 8; nt++)
#pragma unroll
            for (int e = 0; e < 4; e++) s[nt][e] = 0.f;

#pragma unroll
        for (int ks = 0; ks < 4; ks++) {
            uint32_t kh4[4][4];
#pragma unroll
            for (int np = 0; np < 4; np++) {
                int row = np * 16 + (sub & 1) * 8 + r8;
                int ch  = ks * 2 + (sub >> 1);
                ldsm_x4(kh4[np], st + sw128(row, ch));
            }
#pragma unroll
            for (int nt = 0; nt < 8; nt++)
                mma16816(s[nt], qh[ks],
                         kh4[nt >> 1][nt & 1], kh4[nt >> 1][2 + (nt & 1)]);
        }

        // ---- causal mask (diagonal tile only) ----
        if (j == qt) {
            int colb = j * 64;
            int row0 = wr0 + g, row1 = row0 + 8;
#pragma unroll
            for (int nt = 0; nt < 8; nt++) {
                int c0 = colb + nt * 8 + tig * 2;
                if (c0     > row0) s[nt][0] = -1e30f;
                if (c0 + 1 > row0) s[nt][1] = -1e30f;
                if (c0     > row1) s[nt][2] = -1e30f;
                if (c0 + 1 > row1) s[nt][3] = -1e30f;
            }
        }

        // ---- online softmax: row max (quad shuffles) + rescale factors ----
        float mx0 = -1e30f, mx1 = -1e30f;
#pragma unroll
        for (int nt = 0; nt < 8; nt++) {
            mx0 = fmaxf(mx0, fmaxf(s[nt][0], s[nt][1]));
            mx1 = fmaxf(mx1, fmaxf(s[nt][2], s[nt][3]));
        }
        mx0 = fmaxf(mx0, __shfl_xor_sync(0xffffffffu, mx0, 1));
        mx0 = fmaxf(mx0, __shfl_xor_sync(0xffffffffu, mx0, 2));
        mx1 = fmaxf(mx1, __shfl_xor_sync(0xffffffffu, mx1, 1));
        mx1 = fmaxf(mx1, __shfl_xor_sync(0xffffffffu, mx1, 2));
        float nm0 = fmaxf(m0, mx0), nm1 = fmaxf(m1, mx1);
        float cr0 = ex2((m0 - nm0) * Cc), cr1 = ex2((m1 - nm1) * Cc);
        m0 = nm0; m1 = nm1;
        const float mm0 = m0 * Cc, mm1 = m1 * Cc;

        // ---- P fragments: arg in fp32 (FFMA), pack, exp in f16x2 ----
        uint32_t ph[4][4];
#pragma unroll
        for (int j2 = 0; j2 < 4; j2++) {
            float* e0 = s[2 * j2];
            float* e1 = s[2 * j2 + 1];
            ph[j2][0] = ex2h2(pack_f16(fmaf(e0[0], Cc, -mm0), fmaf(e0[1], Cc, -mm0)));
            ph[j2][1] = ex2h2(pack_f16(fmaf(e0[2], Cc, -mm1), fmaf(e0[3], Cc, -mm1)));
            ph[j2][2] = ex2h2(pack_f16(fmaf(e1[0], Cc, -mm0), fmaf(e1[1], Cc, -mm0)));
            ph[j2][3] = ex2h2(pack_f16(fmaf(e1[2], Cc, -mm1), fmaf(e1[3], Cc, -mm1)));
        }

        // ---- rescale O ----
#pragma unroll
        for (int nt = 0; nt < 8; nt++) {
            o[nt][0] *= cr0; o[nt][1] *= cr0;
            o[nt][2] *= cr1; o[nt][3] *= cr1;
        }

        // ---- row sums via MMA with B = ones (off the critical path) ----
        float ls[4] = {0.f, 0.f, 0.f, 0.f};
#pragma unroll
        for (int ks = 0; ks < 4; ks++)
            mma16816(ls, ph[ks], ONES_H2, ONES_H2);
        l0 = l0 * cr0 + ls[0];
        l1 = l1 * cr1 + ls[2];

        // ---- O += P Vh (ldmatrix.trans) ----
#pragma unroll
        for (int ks = 0; ks < 4; ks++) {
#pragma unroll
            for (int dv = 0; dv < 4; dv++) {
                int row = ks * 16 + (sub & 1) * 8 + r8;
                int ch  = dv * 2 + (sub >> 1);
                uint32_t vh4[4];
                ldsm_x4_t(vh4, st + sw128(row, ch) + 8192);
                mma16816(o[2 * dv],     ph[ks], vh4[0], vh4[1]);
                mma16816(o[2 * dv + 1], ph[ks], vh4[2], vh4[3]);
            }
        }
    }

    // ---- normalize + write AO fp16 ----
    float i0 = 1.0f / l0, i1 = 1.0f / l1;
    int t0 = qt * 64 + wid * 16 + g, t1 = t0 + 8;
#pragma unroll
    for (int nt = 0; nt < 8; nt++) {
        int col = nt * 8 + tig * 2;
        *(uint32_t*)&AOh[base + (size_t)t0 * Ev + col] =
            pack_f16(o[nt][0] * i0, o[nt][1] * i0);
        *(uint32_t*)&AOh[base + (size_t)t1 * Ev + col] =
            pack_f16(o[nt][2] * i1, o[nt][3] * i1);
    }
}

// ---------------------------------------------------------------------------
// Launch
// ---------------------------------------------------------------------------
extern "C" void kernel_launch(void* const* d_in, const int* in_sizes, int n_in,
                              void* d_out, int out_size) {
    const float* x  = (const float*)d_in[0];
    const float* Wq = (const float*)d_in[1];
    const float* Wk = (const float*)d_in[2];
    const float* Wv = (const float*)d_in[3];
    const float* Wo = (const float*)d_in[4];
    float* out = (float*)d_out;

    __half *qh, *kh, *vh, *aoh, *xh, *wth;
    cudaGetSymbolAddress((void**)&qh,  g_qh);
    cudaGetSymbolAddress((void**)&kh,  g_kh);
    cudaGetSymbolAddress((void**)&vh,  g_vh);
    cudaGetSymbolAddress((void**)&aoh, g_aoh);
    cudaGetSymbolAddress((void**)&xh,  g_xh);
    cudaGetSymbolAddress((void**)&wth, g_wth);

    static bool attr_set = false;
    if (!attr_set) {
        cudaFuncSetAttribute(gemm_hmma_f16<0>,
                             cudaFuncAttributeMaxDynamicSharedMemorySize, GEMM_SMEM);
        cudaFuncSetAttribute(gemm_hmma_f16<1>,
                             cudaFuncAttributeMaxDynamicSharedMemorySize, GEMM_SMEM);
        cudaFuncSetAttribute(attn_hmma,
                             cudaFuncAttributeMaxDynamicSharedMemorySize, ATT_SMEM);
        attr_set = true;
    }

    const int nElem = MTOK * Ev;

    // 1. x -> fp16
    split_hi4<<<nElem / 1024, 256>>>(x, xh, nElem);

    // 2. transpose all 4 weights to fp16 [N,K]
    dim3 tGrid(Ev / 32, Ev / 32, 4), tBlk(32, 8);
    transpose4<<<tGrid, tBlk>>>(Wq, Wk, Wv, Wo, wth);

    // 3. fused QKV projection (N = 3072, single-term fp16, BK=64)
    dim3 qkvGrid(24, MTOK / BM);
    gemm_hmma_f16<1><<<qkvGrid, 256, GEMM_SMEM>>>(
        xh, wth, nullptr, qh, kh, vh);

    // 4. flash attention (exact R15 kernel)
    dim3 attnGrid(Sv / 64, Bv * Hv);   // (32, 32)
    attn_hmma<<<attnGrid, 128, ATT_SMEM>>>(qh, kh, vh, aoh);

    // 5. output projection -> fp32 out (BK=64)
    dim3 oGrid(Ev / BN, MTOK / BM);
    gemm_hmma_f16<0><<<oGrid, 256, GEMM_SMEM>>>(
        aoh, wth, out, nullptr, nullptr, nullptr);
}